// round 1
// baseline (speedup 1.0000x reference)
#include <cuda_runtime.h>
#include <math.h>

#define BATCH 128
#define HDIM  256
#define CDIM  10
#define HH    (HDIM*HDIM)
#define NDEG  18   // Chebyshev degree

// ---------------- scratch (static device memory; no allocations) ----------------
__device__ __align__(128) float g_Y [BATCH*HH];   // scaled input, eigs in [-1,1]
__device__ __align__(128) float g_Ta[BATCH*HH];   // Chebyshev buffer A
__device__ __align__(128) float g_Tb[BATCH*HH];   // Chebyshev buffer B
__device__ __align__(128) float g_F [BATCH*HH];   // accumulated log(X)
__device__ __align__(128) float g_Ws[CDIM*HH];    // sym(W)
__device__ __align__(128) float g_Msum[HH];       // mean over batch of F
__device__ __align__(128) float g_center[HH];     // sym(mean)
__device__ __align__(128) float g_P[CDIM*HH];     // Ws @ center
__device__ float g_gpart[CDIM];

__device__ __forceinline__ float* Tbuf(int id) { return id == 0 ? g_Ta : g_Tb; }

// ---------------- init: Y = (2X - (a+b)I)/(b-a); T0=I; T1=Y; F=c0*I+c1*Y ------
__global__ void init_kernel(const float* __restrict__ X,
                            float c0, float c1, float sc, float sh)
{
    int idx = blockIdx.x * blockDim.x + threadIdx.x;   // 0 .. BATCH*HH-1
    int rem = idx & (HH - 1);
    int i = rem >> 8, j = rem & 255;
    float x = X[idx];
    float d = (i == j) ? 1.0f : 0.0f;
    float y = (2.0f * x - sh * d) * sc;
    g_Y [idx] = y;
    g_Ta[idx] = d;      // T0 = I
    g_Tb[idx] = y;      // T1 = Y
    g_F [idx] = c0 * d + c1 * y;
}

// ---------------- Ws = 0.5*(W + W^T) ----------------
__global__ void ws_kernel(const float* __restrict__ W)
{
    int idx = blockIdx.x * blockDim.x + threadIdx.x;   // 0 .. CDIM*HH-1
    int c = idx >> 16;          // /HH
    int rem = idx & (HH - 1);
    int i = rem >> 8, j = rem & 255;
    g_Ws[idx] = 0.5f * (W[idx] + W[c * HH + j * 256 + i]);
}

// ---------------- Chebyshev GEMM step: Tnext = 2*Y@Tcur - Tprev; F += ck*Tnext
// next buffer IS the prev buffer (read-then-overwrite per element, same thread).
__global__ void __launch_bounds__(256) cheb_gemm(int cur_id, int next_id, float ck)
{
    const int b = blockIdx.z;
    const float* __restrict__ A  = g_Y + (size_t)b * HH;
    const float* __restrict__ Bm = Tbuf(cur_id)  + (size_t)b * HH;
    float* __restrict__ Cm       = Tbuf(next_id) + (size_t)b * HH;  // holds T_{k-2}
    float* __restrict__ Fm       = g_F + (size_t)b * HH;
    const int tm0 = blockIdx.y * 128, tn0 = blockIdx.x * 128;

    __shared__ float As[8][132];
    __shared__ float Bs[8][128];

    const int t  = threadIdx.x;
    const int tx = t & 15, ty = t >> 4;
    const int arow = t >> 1, akk = (t & 1) * 4;
    const int brow = t >> 5, bcol = (t & 31) * 4;

    float acc[8][8];
#pragma unroll
    for (int i = 0; i < 8; i++)
#pragma unroll
        for (int j = 0; j < 8; j++) acc[i][j] = 0.0f;

    for (int k0 = 0; k0 < 256; k0 += 8) {
        float4 av = *(const float4*)(A  + (tm0 + arow) * 256 + k0 + akk);
        float4 bv = *(const float4*)(Bm + (k0 + brow) * 256 + tn0 + bcol);
        __syncthreads();
        As[akk + 0][arow] = av.x;
        As[akk + 1][arow] = av.y;
        As[akk + 2][arow] = av.z;
        As[akk + 3][arow] = av.w;
        *(float4*)&Bs[brow][bcol] = bv;
        __syncthreads();
#pragma unroll
        for (int kk = 0; kk < 8; kk++) {
            float ar[8], br[8];
#pragma unroll
            for (int i = 0; i < 8; i++) ar[i] = As[kk][ty * 8 + i];
#pragma unroll
            for (int j = 0; j < 8; j++) br[j] = Bs[kk][tx * 8 + j];
#pragma unroll
            for (int i = 0; i < 8; i++)
#pragma unroll
                for (int j = 0; j < 8; j++)
                    acc[i][j] = fmaf(ar[i], br[j], acc[i][j]);
        }
    }

#pragma unroll
    for (int i = 0; i < 8; i++) {
        int row = tm0 + ty * 8 + i;
#pragma unroll
        for (int jq = 0; jq < 2; jq++) {
            int off = row * 256 + tn0 + tx * 8 + jq * 4;
            float4 p = *(const float4*)(Cm + off);   // T_{k-2}
            float4 f = *(const float4*)(Fm + off);
            float4 v;
            v.x = 2.0f * acc[i][jq * 4 + 0] - p.x;
            v.y = 2.0f * acc[i][jq * 4 + 1] - p.y;
            v.z = 2.0f * acc[i][jq * 4 + 2] - p.z;
            v.w = 2.0f * acc[i][jq * 4 + 3] - p.w;
            f.x = fmaf(ck, v.x, f.x);
            f.y = fmaf(ck, v.y, f.y);
            f.z = fmaf(ck, v.z, f.z);
            f.w = fmaf(ck, v.w, f.w);
            *(float4*)(Cm + off) = v;
            *(float4*)(Fm + off) = f;
        }
    }
}

// ---------------- mean over batch ----------------
__global__ void mean_kernel()
{
    int idx = blockIdx.x * blockDim.x + threadIdx.x;   // 0 .. HH-1
    float s = 0.0f;
    for (int b = 0; b < BATCH; b++) s += g_F[(size_t)b * HH + idx];
    g_Msum[idx] = s * (1.0f / BATCH);
}

__global__ void symc_kernel()
{
    int idx = blockIdx.x * blockDim.x + threadIdx.x;   // 0 .. HH-1
    int i = idx >> 8, j = idx & 255;
    g_center[idx] = 0.5f * (g_Msum[idx] + g_Msum[j * 256 + i]);
}

// ---------------- output[b,c] = <Ws[c], F[b]> ----------------
__global__ void out_kernel(float* __restrict__ out)
{
    int b = blockIdx.x, t = threadIdx.x;
    const float4* Fb = (const float4*)(g_F + (size_t)b * HH);
    float acc[CDIM];
#pragma unroll
    for (int c = 0; c < CDIM; c++) acc[c] = 0.0f;
    for (int q = t; q < HH / 4; q += 256) {
        float4 f = Fb[q];
#pragma unroll
        for (int c = 0; c < CDIM; c++) {
            float4 w = ((const float4*)(g_Ws + (size_t)c * HH))[q];
            acc[c] += f.x * w.x + f.y * w.y + f.z * w.z + f.w * w.w;
        }
    }
    __shared__ float red[CDIM][8];
    int lane = t & 31, wp = t >> 5;
#pragma unroll
    for (int c = 0; c < CDIM; c++) {
        float v = acc[c];
        for (int o = 16; o > 0; o >>= 1) v += __shfl_down_sync(0xffffffffu, v, o);
        if (lane == 0) red[c][wp] = v;
    }
    __syncthreads();
    if (t < CDIM) {
        float s = 0.0f;
#pragma unroll
        for (int k = 0; k < 8; k++) s += red[t][k];
        out[b * CDIM + t] = s;
    }
}

// ---------------- P[c] = Ws[c] @ center ----------------
__global__ void __launch_bounds__(256) p_gemm()
{
    const int c = blockIdx.z;
    const float* __restrict__ A  = g_Ws + (size_t)c * HH;
    const float* __restrict__ Bm = g_center;
    float* __restrict__ Cm       = g_P + (size_t)c * HH;
    const int tm0 = blockIdx.y * 128, tn0 = blockIdx.x * 128;

    __shared__ float As[8][132];
    __shared__ float Bs[8][128];
    const int t  = threadIdx.x;
    const int tx = t & 15, ty = t >> 4;
    const int arow = t >> 1, akk = (t & 1) * 4;
    const int brow = t >> 5, bcol = (t & 31) * 4;

    float acc[8][8];
#pragma unroll
    for (int i = 0; i < 8; i++)
#pragma unroll
        for (int j = 0; j < 8; j++) acc[i][j] = 0.0f;

    for (int k0 = 0; k0 < 256; k0 += 8) {
        float4 av = *(const float4*)(A  + (tm0 + arow) * 256 + k0 + akk);
        float4 bv = *(const float4*)(Bm + (k0 + brow) * 256 + tn0 + bcol);
        __syncthreads();
        As[akk + 0][arow] = av.x;
        As[akk + 1][arow] = av.y;
        As[akk + 2][arow] = av.z;
        As[akk + 3][arow] = av.w;
        *(float4*)&Bs[brow][bcol] = bv;
        __syncthreads();
#pragma unroll
        for (int kk = 0; kk < 8; kk++) {
            float ar[8], br[8];
#pragma unroll
            for (int i = 0; i < 8; i++) ar[i] = As[kk][ty * 8 + i];
#pragma unroll
            for (int j = 0; j < 8; j++) br[j] = Bs[kk][tx * 8 + j];
#pragma unroll
            for (int i = 0; i < 8; i++)
#pragma unroll
                for (int j = 0; j < 8; j++)
                    acc[i][j] = fmaf(ar[i], br[j], acc[i][j]);
        }
    }
#pragma unroll
    for (int i = 0; i < 8; i++) {
        int row = tm0 + ty * 8 + i;
#pragma unroll
        for (int jq = 0; jq < 2; jq++) {
            int off = row * 256 + tn0 + tx * 8 + jq * 4;
            float4 v;
            v.x = acc[i][jq * 4 + 0];
            v.y = acc[i][jq * 4 + 1];
            v.z = acc[i][jq * 4 + 2];
            v.w = acc[i][jq * 4 + 3];
            *(float4*)(Cm + off) = v;
        }
    }
}

// ---------------- g[c] = sum_ij P[c,i,j]*P[c,j,i] ----------------
__global__ void gdot_kernel()
{
    int c = blockIdx.x, t = threadIdx.x;
    const float* Pc = g_P + (size_t)c * HH;
    float s = 0.0f;
    for (int idx = t; idx < HH; idx += 256) {
        int i = idx >> 8, j = idx & 255;
        s += Pc[idx] * Pc[j * 256 + i];
    }
    __shared__ float red[8];
    int lane = t & 31, wp = t >> 5;
    for (int o = 16; o > 0; o >>= 1) s += __shfl_down_sync(0xffffffffu, s, o);
    if (lane == 0) red[wp] = s;
    __syncthreads();
    if (t == 0) {
        float v = 0.0f;
#pragma unroll
        for (int k = 0; k < 8; k++) v += red[k];
        g_gpart[c] = v;
    }
}

__global__ void gfinal_kernel(float* __restrict__ out, int out_size)
{
    if (threadIdx.x == 0) {
        float s = 0.0f;
#pragma unroll
        for (int c = 0; c < CDIM; c++) s += g_gpart[c];
        s *= (1.0f / CDIM);
        if (out_size > BATCH * CDIM) out[BATCH * CDIM] = s;
    }
}

// ---------------- host ----------------
extern "C" void kernel_launch(void* const* d_in, const int* in_sizes, int n_in,
                              void* d_out, int out_size)
{
    const float* X = (const float*)d_in[0];   // mat_feats [128,256,256]
    const float* W = (const float*)d_in[1];   // W        [10,256,256]
    float* out = (float*)d_out;

    // Chebyshev coefficients of log on [a,b] (analytic, computed in double)
    const double a = 1.0, b = 6.5;
    const double r = (b - a) / (b + a);
    const double rho = (sqrt(1.0 - r * r) - 1.0) / r;
    float cf[NDEG + 1];
    cf[0] = (float)(log((a + b) * 0.5) - log(1.0 + rho * rho));
    double pk = 1.0;
    for (int k = 1; k <= NDEG; k++) { pk *= rho; cf[k] = (float)(-2.0 * pk / k); }
    const float sc = (float)(1.0 / (b - a));
    const float sh = (float)(a + b);

    init_kernel<<<BATCH * HH / 256, 256>>>(X, cf[0], cf[1], sc, sh);
    ws_kernel<<<CDIM * HH / 256, 256>>>(W);

    dim3 ggrid(2, 2, BATCH);
    for (int k = 2; k <= NDEG; k++) {
        int cur_id = (k - 1) & 1;   // holds T_{k-1}
        int next_id = k & 1;        // holds T_{k-2}, becomes T_k
        cheb_gemm<<<ggrid, 256>>>(cur_id, next_id, cf[k]);
    }

    mean_kernel<<<HH / 256, 256>>>();
    symc_kernel<<<HH / 256, 256>>>();
    out_kernel<<<BATCH, 256>>>(out);
    p_gemm<<<dim3(2, 2, CDIM), 256>>>();
    gdot_kernel<<<CDIM, 256>>>();
    gfinal_kernel<<<1, 32>>>(out, out_size);
}

// round 7
// speedup vs baseline: 1.1727x; 1.1727x over previous
#include <cuda_runtime.h>
#include <math.h>
#include <stdint.h>

#define BATCH 128
#define HDIM  256
#define CDIM  10
#define HH    (HDIM*HDIM)

// ---------------- static device buffers ----------------
__device__ __align__(128) float g_Y [BATCH*HH];
__device__ __align__(128) float g_T2[BATCH*HH];
__device__ __align__(128) float g_T3[BATCH*HH];
__device__ __align__(128) float g_T4[BATCH*HH];
__device__ __align__(128) float g_T8[BATCH*HH];
__device__ __align__(128) float g_U [BATCH*HH];
__device__ __align__(128) float g_V [BATCH*HH];
__device__ __align__(128) float g_F [BATCH*HH];
__device__ __align__(128) float g_Ws[CDIM*HH];
__device__ __align__(128) float g_center[HH];
__device__ __align__(128) float g_P[CDIM*HH];
__device__ float g_gpart[CDIM];

__device__ __forceinline__ float* bufptr(int id) {
    switch (id) {
        case 0: return g_Y;  case 1: return g_T2; case 2: return g_T3;
        case 3: return g_T4; case 4: return g_T8; case 5: return g_U;
        case 6: return g_V;  default: return g_F;
    }
}

// ---------------- init: Y = (2X - (a+b)I) * sc ----------------
__global__ void init_kernel(const float* __restrict__ X, float sc, float sh)
{
    int q = blockIdx.x * blockDim.x + threadIdx.x;     // over BATCH*HH/4
    float4 x = ((const float4*)X)[q];
    int rem = (q << 2) & (HH - 1);
    int i = rem >> 8;
    int dp = i - (rem & 255);                          // 0..3 if diagonal in this float4
    float4 y;
    y.x = 2.0f * x.x; y.y = 2.0f * x.y; y.z = 2.0f * x.z; y.w = 2.0f * x.w;
    if ((unsigned)dp < 4u) (&y.x)[dp] -= sh;
    y.x *= sc; y.y *= sc; y.z *= sc; y.w *= sc;
    ((float4*)g_Y)[q] = y;
}

// ---------------- Ws = 0.5*(W + W^T) ----------------
__global__ void ws_kernel(const float* __restrict__ W)
{
    int idx = blockIdx.x * blockDim.x + threadIdx.x;   // over CDIM*HH
    int c = idx >> 16;
    int rem = idx & (HH - 1);
    int i = rem >> 8, j = rem & 255;
    g_Ws[idx] = 0.5f * (W[idx] + W[c * HH + j * 256 + i]);
}

// ---------------- symmetric-product GEMM ----------------
// C_tile = op( A @ B ), where A,B are symmetric commuting (product symmetric).
// grid = (3, BATCH): tile 0=(0,0), 1=(128,128), 2=(128,0)+mirror(0,128)
// MODE 0: C = 2*acc - I        (T2=2YY-I, T4=2T2T2-I, T8=2T4T4-I)
// MODE 1: C = 2*acc - D        (T3=2*Y*T2 - Y)
// MODE 2: C += 2*acc, K=512    (F += 2*(T4*U + T8*V)) via A2/B2 second phase
template<int MODE>
__global__ void __launch_bounds__(256, 3) gemm_sym(int ida, int idb, int ida2,
                                                   int idb2, int idd, int idc)
{
    __shared__ __align__(16) float As[2][128][12];
    __shared__ __align__(16) float Bs[2][8][128];

    const float* __restrict__ gA  = bufptr(ida);
    const float* __restrict__ gB  = bufptr(idb);
    const float* __restrict__ gA2 = bufptr(ida2);
    const float* __restrict__ gB2 = bufptr(idb2);
    const float* __restrict__ gD  = bufptr(idd);
    float* __restrict__ gC        = bufptr(idc);

    const int b = blockIdx.y;
    const size_t base = (size_t)b * HH;
    const int tile = blockIdx.x;
    const int tm0 = (tile == 0) ? 0 : 128;
    const int tn0 = (tile == 1) ? 128 : 0;
    const int t = threadIdx.x;
    const int tx = t & 15, ty = t >> 4;

    const int arow = t >> 1, aoff = (t & 1) * 4;
    const int brow = t >> 5, bcol = (t & 31) * 4;

    const int KTOT = (MODE == 2) ? 512 : 256;

    uint32_t as0 = (uint32_t)__cvta_generic_to_shared(&As[0][0][0]);
    uint32_t bs0 = (uint32_t)__cvta_generic_to_shared(&Bs[0][0][0]);

    auto issue = [&](int buf, int kg) {
        const float* A = (kg < 256) ? gA : gA2;
        const float* B = (kg < 256) ? gB : gB2;
        int k = kg & 255;
        const float* asrc = A + base + (size_t)(tm0 + arow) * 256 + k + aoff;
        const float* bsrc = B + base + (size_t)(k + brow) * 256 + tn0 + bcol;
        uint32_t adst = as0 + (uint32_t)(buf * 1536 + arow * 12 + aoff) * 4u;
        uint32_t bdst = bs0 + (uint32_t)(buf * 1024 + brow * 128 + bcol) * 4u;
        asm volatile("cp.async.ca.shared.global [%0], [%1], 16;\n" :: "r"(adst), "l"(asrc) : "memory");
        asm volatile("cp.async.ca.shared.global [%0], [%1], 16;\n" :: "r"(bdst), "l"(bsrc) : "memory");
        asm volatile("cp.async.commit_group;\n" ::: "memory");
    };

    float acc[8][8];
#pragma unroll
    for (int i = 0; i < 8; i++)
#pragma unroll
        for (int j = 0; j < 8; j++) acc[i][j] = 0.0f;

    issue(0, 0);
    int cur = 0;
    for (int kg = 0; kg < KTOT; kg += 8) {
        asm volatile("cp.async.wait_group 0;\n" ::: "memory");
        __syncthreads();
        if (kg + 8 < KTOT) issue(cur ^ 1, kg + 8);
#pragma unroll
        for (int kk = 0; kk < 8; kk++) {
            float ar[8], br[8];
            float4 b0 = *(const float4*)&Bs[cur][kk][tx * 8];
            float4 b1 = *(const float4*)&Bs[cur][kk][tx * 8 + 4];
            br[0] = b0.x; br[1] = b0.y; br[2] = b0.z; br[3] = b0.w;
            br[4] = b1.x; br[5] = b1.y; br[6] = b1.z; br[7] = b1.w;
#pragma unroll
            for (int i = 0; i < 8; i++) ar[i] = As[cur][ty * 8 + i][kk];
#pragma unroll
            for (int i = 0; i < 8; i++)
#pragma unroll
                for (int j = 0; j < 8; j++)
                    acc[i][j] = fmaf(ar[i], br[j], acc[i][j]);
        }
        cur ^= 1;
    }

    // main tile epilogue
#pragma unroll
    for (int i = 0; i < 8; i++) {
        int row = tm0 + ty * 8 + i;
#pragma unroll
        for (int jq = 0; jq < 2; jq++) {
            int col = tn0 + tx * 8 + jq * 4;
            size_t off = base + (size_t)row * 256 + col;
            float4 v;
            v.x = 2.0f * acc[i][jq * 4 + 0];
            v.y = 2.0f * acc[i][jq * 4 + 1];
            v.z = 2.0f * acc[i][jq * 4 + 2];
            v.w = 2.0f * acc[i][jq * 4 + 3];
            if (MODE == 0) {
                int d = row - col;
                if ((unsigned)d < 4u) (&v.x)[d] -= 1.0f;
            } else if (MODE == 1) {
                float4 dd = *(const float4*)(gD + off);
                v.x -= dd.x; v.y -= dd.y; v.z -= dd.z; v.w -= dd.w;
            } else {
                float4 f = *(const float4*)(gC + off);
                v.x += f.x; v.y += f.y; v.z += f.z; v.w += f.w;
            }
            *(float4*)(gC + off) = v;
        }
    }

    // mirror tile (transpose) for off-diagonal block
    if (tile == 2) {
#pragma unroll
        for (int j = 0; j < 8; j++) {
            int mrow = tx * 8 + j;                    // tn0 == 0
#pragma unroll
            for (int iq = 0; iq < 2; iq++) {
                int mcol = tm0 + ty * 8 + iq * 4;
                size_t off = base + (size_t)mrow * 256 + mcol;
                float4 v;
                v.x = 2.0f * acc[iq * 4 + 0][j];
                v.y = 2.0f * acc[iq * 4 + 1][j];
                v.z = 2.0f * acc[iq * 4 + 2][j];
                v.w = 2.0f * acc[iq * 4 + 3][j];
                if (MODE == 1) {
                    float4 dd = *(const float4*)(gD + off);
                    v.x -= dd.x; v.y -= dd.y; v.z -= dd.z; v.w -= dd.w;
                } else if (MODE == 2) {
                    float4 f = *(const float4*)(gC + off);
                    v.x += f.x; v.y += f.y; v.z += f.z; v.w += f.w;
                }
                *(float4*)(gC + off) = v;
            }
        }
    }
}

// ---------------- combo: U, V, F(=D0) from T1..T4,T8 ----------------
__global__ void combo_kernel(float a5, float a6, float a7,
                             float c9, float c10, float c11, float c12,
                             float c0, float b1, float b2, float b3, float b4,
                             float c8)
{
    int q = blockIdx.x * blockDim.x + threadIdx.x;    // over BATCH*HH/4
    float4 y  = ((const float4*)g_Y )[q];
    float4 t2 = ((const float4*)g_T2)[q];
    float4 t3 = ((const float4*)g_T3)[q];
    float4 t4 = ((const float4*)g_T4)[q];
    float4 t8 = ((const float4*)g_T8)[q];
    float4 u, v, f;
#define EW(e) \
    u.e = a5 * y.e + a6 * t2.e + a7 * t3.e; \
    v.e = c9 * y.e + c10 * t2.e + c11 * t3.e + c12 * t4.e; \
    f.e = b1 * y.e + b2 * t2.e + b3 * t3.e + b4 * t4.e + c8 * t8.e;
    EW(x) EW(y) EW(z) EW(w)
#undef EW
    int rem = (q << 2) & (HH - 1);
    int dp = (rem >> 8) - (rem & 255);
    if ((unsigned)dp < 4u) (&f.x)[dp] += c0;
    ((float4*)g_U)[q] = u;
    ((float4*)g_V)[q] = v;
    ((float4*)g_F)[q] = f;
}

// ---------------- fused: center = sym(mean_b F) ----------------
// center[i,j] = 0.5*( mean_b F[b,i,j] + mean_b F[b,j,i] )
__global__ void center_kernel()
{
    int idx = blockIdx.x * blockDim.x + threadIdx.x;   // over HH
    int i = idx >> 8, j = idx & 255;
    int tidx = j * 256 + i;
    float s = 0.0f, st = 0.0f;
    for (int b = 0; b < BATCH; b++) {
        const float* Fb = g_F + (size_t)b * HH;
        s  += Fb[idx];
        st += Fb[tidx];
    }
    g_center[idx] = 0.5f * (s + st) * (1.0f / BATCH);
}

// ---------------- output[b,c] = <Ws[c], F[b]> ----------------
__global__ void out_kernel(float* __restrict__ out)
{
    int b = blockIdx.x, t = threadIdx.x;
    const float4* Fb = (const float4*)(g_F + (size_t)b * HH);
    float acc[CDIM];
#pragma unroll
    for (int c = 0; c < CDIM; c++) acc[c] = 0.0f;
    for (int q = t; q < HH / 4; q += 256) {
        float4 f = Fb[q];
#pragma unroll
        for (int c = 0; c < CDIM; c++) {
            float4 w = ((const float4*)(g_Ws + (size_t)c * HH))[q];
            acc[c] += f.x * w.x + f.y * w.y + f.z * w.z + f.w * w.w;
        }
    }
    __shared__ float red[CDIM][8];
    int lane = t & 31, wp = t >> 5;
#pragma unroll
    for (int c = 0; c < CDIM; c++) {
        float v = acc[c];
        for (int o = 16; o > 0; o >>= 1) v += __shfl_down_sync(0xffffffffu, v, o);
        if (lane == 0) red[c][wp] = v;
    }
    __syncthreads();
    if (t < CDIM) {
        float s = 0.0f;
#pragma unroll
        for (int k = 0; k < 8; k++) s += red[t][k];
        out[b * CDIM + t] = s;
    }
}

// ---------------- P[c] = Ws[c] @ center ----------------
__global__ void __launch_bounds__(256) p_gemm()
{
    const int c = blockIdx.z;
    const float* __restrict__ A  = g_Ws + (size_t)c * HH;
    const float* __restrict__ Bm = g_center;
    float* __restrict__ Cm       = g_P + (size_t)c * HH;
    const int tm0 = blockIdx.y * 128, tn0 = blockIdx.x * 128;

    __shared__ float As[8][132];
    __shared__ float Bs[8][128];
    const int t  = threadIdx.x;
    const int tx = t & 15, ty = t >> 4;
    const int arow = t >> 1, akk = (t & 1) * 4;
    const int brow = t >> 5, bcol = (t & 31) * 4;

    float acc[8][8];
#pragma unroll
    for (int i = 0; i < 8; i++)
#pragma unroll
        for (int j = 0; j < 8; j++) acc[i][j] = 0.0f;

    for (int k0 = 0; k0 < 256; k0 += 8) {
        float4 av = *(const float4*)(A  + (tm0 + arow) * 256 + k0 + akk);
        float4 bv = *(const float4*)(Bm + (k0 + brow) * 256 + tn0 + bcol);
        __syncthreads();
        As[akk + 0][arow] = av.x;
        As[akk + 1][arow] = av.y;
        As[akk + 2][arow] = av.z;
        As[akk + 3][arow] = av.w;
        *(float4*)&Bs[brow][bcol] = bv;
        __syncthreads();
#pragma unroll
        for (int kk = 0; kk < 8; kk++) {
            float ar[8], br[8];
#pragma unroll
            for (int i = 0; i < 8; i++) ar[i] = As[kk][ty * 8 + i];
#pragma unroll
            for (int j = 0; j < 8; j++) br[j] = Bs[kk][tx * 8 + j];
#pragma unroll
            for (int i = 0; i < 8; i++)
#pragma unroll
                for (int j = 0; j < 8; j++)
                    acc[i][j] = fmaf(ar[i], br[j], acc[i][j]);
        }
    }
#pragma unroll
    for (int i = 0; i < 8; i++) {
        int row = tm0 + ty * 8 + i;
#pragma unroll
        for (int jq = 0; jq < 2; jq++) {
            int off = row * 256 + tn0 + tx * 8 + jq * 4;
            float4 v;
            v.x = acc[i][jq * 4 + 0];
            v.y = acc[i][jq * 4 + 1];
            v.z = acc[i][jq * 4 + 2];
            v.w = acc[i][jq * 4 + 3];
            *(float4*)(Cm + off) = v;
        }
    }
}

// ---------------- g[c] = sum_ij P[c,i,j]*P[c,j,i] ----------------
__global__ void gdot_kernel()
{
    int c = blockIdx.x, t = threadIdx.x;
    const float* Pc = g_P + (size_t)c * HH;
    float s = 0.0f;
    for (int idx = t; idx < HH; idx += 256) {
        int i = idx >> 8, j = idx & 255;
        s += Pc[idx] * Pc[j * 256 + i];
    }
    __shared__ float red[8];
    int lane = t & 31, wp = t >> 5;
    for (int o = 16; o > 0; o >>= 1) s += __shfl_down_sync(0xffffffffu, s, o);
    if (lane == 0) red[wp] = s;
    __syncthreads();
    if (t == 0) {
        float v = 0.0f;
#pragma unroll
        for (int k = 0; k < 8; k++) v += red[k];
        g_gpart[c] = v;
    }
}

__global__ void gfinal_kernel(float* __restrict__ out, int out_size)
{
    if (threadIdx.x == 0) {
        float s = 0.0f;
#pragma unroll
        for (int c = 0; c < CDIM; c++) s += g_gpart[c];
        s *= (1.0f / CDIM);
        if (out_size > BATCH * CDIM) out[BATCH * CDIM] = s;
    }
}

// ---------------- host ----------------
extern "C" void kernel_launch(void* const* d_in, const int* in_sizes, int n_in,
                              void* d_out, int out_size)
{
    const float* X = (const float*)d_in[0];   // mat_feats [128,256,256]
    const float* W = (const float*)d_in[1];   // W        [10,256,256]
    float* out = (float*)d_out;

    // Chebyshev coefficients of log on [a,b]: log(A+Bt) = logC - 2 sum rho^k/k T_k
    const double a = 1.0, b = 6.5;
    const double r = (b - a) / (b + a);
    const double rho = (sqrt(1.0 - r * r) - 1.0) / r;   // -0.4365
    float c[13];
    c[0] = (float)(log((a + b) * 0.5) - log(1.0 + rho * rho));
    double pk = 1.0;
    for (int k = 1; k <= 12; k++) { pk *= rho; c[k] = (float)(-2.0 * pk / k); }
    const float sc = (float)(1.0 / (b - a));
    const float sh = (float)(a + b);

    const float a5 = c[5] - c[11], a6 = c[6] - c[10], a7 = c[7] - c[9];
    const float b1 = c[1] - c[7] + c[9];
    const float b2 = c[2] - c[6] + c[10];
    const float b3 = c[3] - c[5] + c[11];
    const float b4 = c[4] - c[12];

    init_kernel<<<BATCH * HH / 4 / 256, 256>>>(X, sc, sh);
    ws_kernel<<<CDIM * HH / 256, 256>>>(W);

    dim3 gg(3, BATCH);
    // buffer ids: 0=Y 1=T2 2=T3 3=T4 4=T8 5=U 6=V 7=F
    gemm_sym<0><<<gg, 256>>>(0, 0, 0, 0, 0, 1);   // T2 = 2*Y*Y - I
    gemm_sym<1><<<gg, 256>>>(0, 1, 0, 0, 0, 2);   // T3 = 2*Y*T2 - Y
    gemm_sym<0><<<gg, 256>>>(1, 1, 0, 0, 0, 3);   // T4 = 2*T2*T2 - I
    gemm_sym<0><<<gg, 256>>>(3, 3, 0, 0, 0, 4);   // T8 = 2*T4*T4 - I

    combo_kernel<<<BATCH * HH / 4 / 256, 256>>>(a5, a6, a7,
                                                c[9], c[10], c[11], c[12],
                                                c[0], b1, b2, b3, b4, c[8]);

    gemm_sym<2><<<gg, 256>>>(3, 5, 4, 6, 0, 7);   // F += 2*(T4*U + T8*V), K=512

    center_kernel<<<HH / 256, 256>>>();
    out_kernel<<<BATCH, 256>>>(out);
    p_gemm<<<dim3(2, 2, CDIM), 256>>>();
    gdot_kernel<<<CDIM, 256>>>();
    gfinal_kernel<<<1, 32>>>(out, out_size);
}

// round 10
// speedup vs baseline: 2.1385x; 1.8235x over previous
#include <cuda_runtime.h>
#include <math.h>
#include <stdint.h>

#define BATCH 128
#define HDIM  256
#define CDIM  10
#define HH    (HDIM*HDIM)

// ---------------- static device buffers ----------------
__device__ __align__(128) float g_Y [BATCH*HH];
__device__ __align__(128) float g_T2[BATCH*HH];
__device__ __align__(128) float g_T3[BATCH*HH];
__device__ __align__(128) float g_T4[BATCH*HH];
__device__ __align__(128) float g_T8[BATCH*HH];
__device__ __align__(128) float g_U [BATCH*HH];
__device__ __align__(128) float g_V [BATCH*HH];
__device__ __align__(128) float g_F [BATCH*HH];
__device__ __align__(128) float g_Ws[CDIM*HH];
__device__ __align__(128) float g_center[HH];
__device__ __align__(128) float g_P[CDIM*HH];
__device__ float g_gpart[CDIM];

__device__ __forceinline__ float* bufptr(int id) {
    switch (id) {
        case 0: return g_Y;  case 1: return g_T2; case 2: return g_T3;
        case 3: return g_T4; case 4: return g_T8; case 5: return g_U;
        case 6: return g_V;  default: return g_F;
    }
}

// ---------------- init: Y = (2X - (a+b)I) * sc ----------------
__global__ void init_kernel(const float* __restrict__ X, float sc, float sh)
{
    int q = blockIdx.x * blockDim.x + threadIdx.x;     // over BATCH*HH/4
    float4 x = ((const float4*)X)[q];
    int rem = (q << 2) & (HH - 1);
    int i = rem >> 8;
    int dp = i - (rem & 255);                          // 0..3 if diagonal in this float4
    float4 y;
    y.x = 2.0f * x.x; y.y = 2.0f * x.y; y.z = 2.0f * x.z; y.w = 2.0f * x.w;
    if ((unsigned)dp < 4u) (&y.x)[dp] -= sh;
    y.x *= sc; y.y *= sc; y.z *= sc; y.w *= sc;
    ((float4*)g_Y)[q] = y;
}

// ---------------- Ws = 0.5*(W + W^T) ----------------
__global__ void ws_kernel(const float* __restrict__ W)
{
    int idx = blockIdx.x * blockDim.x + threadIdx.x;   // over CDIM*HH
    int c = idx >> 16;
    int rem = idx & (HH - 1);
    int i = rem >> 8, j = rem & 255;
    g_Ws[idx] = 0.5f * (W[idx] + W[c * HH + j * 256 + i]);
}

// ---------------- symmetric-operand GEMM ----------------
// All A operands are SYMMETRIC, so the A tile is loaded K-MAJOR directly:
//   As[kk][i] = A[k0+kk][tm0+i] == A[tm0+i][k0+kk]
// giving contiguous cp.async copies AND contiguous (vectorizable, conflict-free)
// LDS reads for both A and B in the inner loop.
// grid = (3, BATCH): tile 0=(0,0), 1=(128,128), 2=(128,0)+mirror(0,128)
// MODE 0: C = 2*acc - I        (T2=2YY-I, T4=2T2T2-I, T8=2T4T4-I)
// MODE 1: C = 2*acc - D        (T3=2*Y*T2 - Y)
// MODE 2: C += 2*acc, K=512    (F += 2*(T4*U + T8*V)) via A2/B2 second phase
template<int MODE>
__global__ void __launch_bounds__(256, 3) gemm_sym(int ida, int idb, int ida2,
                                                   int idb2, int idd, int idc)
{
    __shared__ __align__(16) float As[2][8][128];
    __shared__ __align__(16) float Bs[2][8][128];

    const float* __restrict__ gA  = bufptr(ida);
    const float* __restrict__ gB  = bufptr(idb);
    const float* __restrict__ gA2 = bufptr(ida2);
    const float* __restrict__ gB2 = bufptr(idb2);
    const float* __restrict__ gD  = bufptr(idd);
    float* __restrict__ gC        = bufptr(idc);

    const int b = blockIdx.y;
    const size_t base = (size_t)b * HH;
    const int tile = blockIdx.x;
    const int tm0 = (tile == 0) ? 0 : 128;
    const int tn0 = (tile == 1) ? 128 : 0;
    const int t = threadIdx.x;
    const int tx = t & 15, ty = t >> 4;

    const int crow = t >> 5, ccol = (t & 31) * 4;   // copy row (k), col (4 floats)

    const int KTOT = (MODE == 2) ? 512 : 256;

    uint32_t as0 = (uint32_t)__cvta_generic_to_shared(&As[0][0][0]);
    uint32_t bs0 = (uint32_t)__cvta_generic_to_shared(&Bs[0][0][0]);

    auto issue = [&](int buf, int kg) {
        const float* A = (kg < 256) ? gA : gA2;
        const float* B = (kg < 256) ? gB : gB2;
        int k = kg & 255;
        // A tile loaded K-MAJOR (valid because A is symmetric)
        const float* asrc = A + base + (size_t)(k + crow) * 256 + tm0 + ccol;
        const float* bsrc = B + base + (size_t)(k + crow) * 256 + tn0 + ccol;
        uint32_t adst = as0 + (uint32_t)(buf * 1024 + crow * 128 + ccol) * 4u;
        uint32_t bdst = bs0 + (uint32_t)(buf * 1024 + crow * 128 + ccol) * 4u;
        asm volatile("cp.async.ca.shared.global [%0], [%1], 16;\n" :: "r"(adst), "l"(asrc) : "memory");
        asm volatile("cp.async.ca.shared.global [%0], [%1], 16;\n" :: "r"(bdst), "l"(bsrc) : "memory");
        asm volatile("cp.async.commit_group;\n" ::: "memory");
    };

    float acc[8][8];
#pragma unroll
    for (int i = 0; i < 8; i++)
#pragma unroll
        for (int j = 0; j < 8; j++) acc[i][j] = 0.0f;

    issue(0, 0);
    int cur = 0;
    for (int kg = 0; kg < KTOT; kg += 8) {
        asm volatile("cp.async.wait_group 0;\n" ::: "memory");
        __syncthreads();
        if (kg + 8 < KTOT) issue(cur ^ 1, kg + 8);
#pragma unroll
        for (int kk = 0; kk < 8; kk++) {
            float ar[8], br[8];
            float4 a0 = *(const float4*)&As[cur][kk][ty * 8];
            float4 a1 = *(const float4*)&As[cur][kk][ty * 8 + 4];
            ar[0] = a0.x; ar[1] = a0.y; ar[2] = a0.z; ar[3] = a0.w;
            ar[4] = a1.x; ar[5] = a1.y; ar[6] = a1.z; ar[7] = a1.w;
            float4 b0 = *(const float4*)&Bs[cur][kk][tx * 8];
            float4 b1 = *(const float4*)&Bs[cur][kk][tx * 8 + 4];
            br[0] = b0.x; br[1] = b0.y; br[2] = b0.z; br[3] = b0.w;
            br[4] = b1.x; br[5] = b1.y; br[6] = b1.z; br[7] = b1.w;
#pragma unroll
            for (int i = 0; i < 8; i++)
#pragma unroll
                for (int j = 0; j < 8; j++)
                    acc[i][j] = fmaf(ar[i], br[j], acc[i][j]);
        }
        cur ^= 1;
    }

    // main tile epilogue
#pragma unroll
    for (int i = 0; i < 8; i++) {
        int row = tm0 + ty * 8 + i;
#pragma unroll
        for (int jq = 0; jq < 2; jq++) {
            int col = tn0 + tx * 8 + jq * 4;
            size_t off = base + (size_t)row * 256 + col;
            float4 v;
            v.x = 2.0f * acc[i][jq * 4 + 0];
            v.y = 2.0f * acc[i][jq * 4 + 1];
            v.z = 2.0f * acc[i][jq * 4 + 2];
            v.w = 2.0f * acc[i][jq * 4 + 3];
            if (MODE == 0) {
                int d = row - col;
                if ((unsigned)d < 4u) (&v.x)[d] -= 1.0f;
            } else if (MODE == 1) {
                float4 dd = *(const float4*)(gD + off);
                v.x -= dd.x; v.y -= dd.y; v.z -= dd.z; v.w -= dd.w;
            } else {
                float4 f = *(const float4*)(gC + off);
                v.x += f.x; v.y += f.y; v.z += f.z; v.w += f.w;
            }
            *(float4*)(gC + off) = v;
        }
    }

    // mirror tile (transpose) for off-diagonal block
    if (tile == 2) {
#pragma unroll
        for (int j = 0; j < 8; j++) {
            int mrow = tx * 8 + j;                    // tn0 == 0
#pragma unroll
            for (int iq = 0; iq < 2; iq++) {
                int mcol = tm0 + ty * 8 + iq * 4;
                size_t off = base + (size_t)mrow * 256 + mcol;
                float4 v;
                v.x = 2.0f * acc[iq * 4 + 0][j];
                v.y = 2.0f * acc[iq * 4 + 1][j];
                v.z = 2.0f * acc[iq * 4 + 2][j];
                v.w = 2.0f * acc[iq * 4 + 3][j];
                if (MODE == 1) {
                    float4 dd = *(const float4*)(gD + off);
                    v.x -= dd.x; v.y -= dd.y; v.z -= dd.z; v.w -= dd.w;
                } else if (MODE == 2) {
                    float4 f = *(const float4*)(gC + off);
                    v.x += f.x; v.y += f.y; v.z += f.z; v.w += f.w;
                }
                *(float4*)(gC + off) = v;
            }
        }
    }
}

// ---------------- combo: U, V, F(=D0) from T1..T4,T8 ----------------
__global__ void combo_kernel(float a5, float a6, float a7,
                             float c9, float c10, float c11, float c12,
                             float c0, float b1, float b2, float b3, float b4,
                             float c8)
{
    int q = blockIdx.x * blockDim.x + threadIdx.x;    // over BATCH*HH/4
    float4 y  = ((const float4*)g_Y )[q];
    float4 t2 = ((const float4*)g_T2)[q];
    float4 t3 = ((const float4*)g_T3)[q];
    float4 t4 = ((const float4*)g_T4)[q];
    float4 t8 = ((const float4*)g_T8)[q];
    float4 u, v, f;
#define EW(e) \
    u.e = a5 * y.e + a6 * t2.e + a7 * t3.e; \
    v.e = c9 * y.e + c10 * t2.e + c11 * t3.e + c12 * t4.e; \
    f.e = b1 * y.e + b2 * t2.e + b3 * t3.e + b4 * t4.e + c8 * t8.e;
    EW(x) EW(y) EW(z) EW(w)
#undef EW
    int rem = (q << 2) & (HH - 1);
    int dp = (rem >> 8) - (rem & 255);
    if ((unsigned)dp < 4u) (&f.x)[dp] += c0;
    ((float4*)g_U)[q] = u;
    ((float4*)g_V)[q] = v;
    ((float4*)g_F)[q] = f;
}

// ---------------- fused: center = sym(mean_b F) ----------------
__global__ void center_kernel()
{
    int idx = blockIdx.x * blockDim.x + threadIdx.x;   // over HH
    int i = idx >> 8, j = idx & 255;
    int tidx = j * 256 + i;
    float s = 0.0f, st = 0.0f;
    for (int b = 0; b < BATCH; b++) {
        const float* Fb = g_F + (size_t)b * HH;
        s  += Fb[idx];
        st += Fb[tidx];
    }
    g_center[idx] = 0.5f * (s + st) * (1.0f / BATCH);
}

// ---------------- output[b,c] = <Ws[c], F[b]> ----------------
__global__ void out_kernel(float* __restrict__ out)
{
    int b = blockIdx.x, t = threadIdx.x;
    const float4* Fb = (const float4*)(g_F + (size_t)b * HH);
    float acc[CDIM];
#pragma unroll
    for (int c = 0; c < CDIM; c++) acc[c] = 0.0f;
    for (int q = t; q < HH / 4; q += 256) {
        float4 f = Fb[q];
#pragma unroll
        for (int c = 0; c < CDIM; c++) {
            float4 w = ((const float4*)(g_Ws + (size_t)c * HH))[q];
            acc[c] += f.x * w.x + f.y * w.y + f.z * w.z + f.w * w.w;
        }
    }
    __shared__ float red[CDIM][8];
    int lane = t & 31, wp = t >> 5;
#pragma unroll
    for (int c = 0; c < CDIM; c++) {
        float v = acc[c];
        for (int o = 16; o > 0; o >>= 1) v += __shfl_down_sync(0xffffffffu, v, o);
        if (lane == 0) red[c][wp] = v;
    }
    __syncthreads();
    if (t < CDIM) {
        float s = 0.0f;
#pragma unroll
        for (int k = 0; k < 8; k++) s += red[t][k];
        out[b * CDIM + t] = s;
    }
}

// ---------------- P[c] = Ws[c] @ center ----------------
__global__ void __launch_bounds__(256) p_gemm()
{
    const int c = blockIdx.z;
    const float* __restrict__ A  = g_Ws + (size_t)c * HH;
    const float* __restrict__ Bm = g_center;
    float* __restrict__ Cm       = g_P + (size_t)c * HH;
    const int tm0 = blockIdx.y * 128, tn0 = blockIdx.x * 128;

    __shared__ float As[8][132];
    __shared__ float Bs[8][128];
    const int t  = threadIdx.x;
    const int tx = t & 15, ty = t >> 4;
    const int arow = t >> 1, akk = (t & 1) * 4;
    const int brow = t >> 5, bcol = (t & 31) * 4;

    float acc[8][8];
#pragma unroll
    for (int i = 0; i < 8; i++)
#pragma unroll
        for (int j = 0; j < 8; j++) acc[i][j] = 0.0f;

    for (int k0 = 0; k0 < 256; k0 += 8) {
        float4 av = *(const float4*)(A  + (tm0 + arow) * 256 + k0 + akk);
        float4 bv = *(const float4*)(Bm + (k0 + brow) * 256 + tn0 + bcol);
        __syncthreads();
        As[akk + 0][arow] = av.x;
        As[akk + 1][arow] = av.y;
        As[akk + 2][arow] = av.z;
        As[akk + 3][arow] = av.w;
        *(float4*)&Bs[brow][bcol] = bv;
        __syncthreads();
#pragma unroll
        for (int kk = 0; kk < 8; kk++) {
            float ar[8], br[8];
#pragma unroll
            for (int i = 0; i < 8; i++) ar[i] = As[kk][ty * 8 + i];
#pragma unroll
            for (int j = 0; j < 8; j++) br[j] = Bs[kk][tx * 8 + j];
#pragma unroll
            for (int i = 0; i < 8; i++)
#pragma unroll
                for (int j = 0; j < 8; j++)
                    acc[i][j] = fmaf(ar[i], br[j], acc[i][j]);
        }
    }
#pragma unroll
    for (int i = 0; i < 8; i++) {
        int row = tm0 + ty * 8 + i;
#pragma unroll
        for (int jq = 0; jq < 2; jq++) {
            int off = row * 256 + tn0 + tx * 8 + jq * 4;
            float4 v;
            v.x = acc[i][jq * 4 + 0];
            v.y = acc[i][jq * 4 + 1];
            v.z = acc[i][jq * 4 + 2];
            v.w = acc[i][jq * 4 + 3];
            *(float4*)(Cm + off) = v;
        }
    }
}

// ---------------- g[c] = sum_ij P[c,i,j]*P[c,j,i] ----------------
__global__ void gdot_kernel()
{
    int c = blockIdx.x, t = threadIdx.x;
    const float* Pc = g_P + (size_t)c * HH;
    float s = 0.0f;
    for (int idx = t; idx < HH; idx += 256) {
        int i = idx >> 8, j = idx & 255;
        s += Pc[idx] * Pc[j * 256 + i];
    }
    __shared__ float red[8];
    int lane = t & 31, wp = t >> 5;
    for (int o = 16; o > 0; o >>= 1) s += __shfl_down_sync(0xffffffffu, s, o);
    if (lane == 0) red[wp] = s;
    __syncthreads();
    if (t == 0) {
        float v = 0.0f;
#pragma unroll
        for (int k = 0; k < 8; k++) v += red[k];
        g_gpart[c] = v;
    }
}

__global__ void gfinal_kernel(float* __restrict__ out, int out_size)
{
    if (threadIdx.x == 0) {
        float s = 0.0f;
#pragma unroll
        for (int c = 0; c < CDIM; c++) s += g_gpart[c];
        s *= (1.0f / CDIM);
        if (out_size > BATCH * CDIM) out[BATCH * CDIM] = s;
    }
}

// ---------------- host ----------------
extern "C" void kernel_launch(void* const* d_in, const int* in_sizes, int n_in,
                              void* d_out, int out_size)
{
    const float* X = (const float*)d_in[0];   // mat_feats [128,256,256]
    const float* W = (const float*)d_in[1];   // W        [10,256,256]
    float* out = (float*)d_out;

    // Chebyshev coefficients of log on [a,b]: log(A+Bt) = logC - 2 sum rho^k/k T_k
    const double a = 1.0, b = 6.5;
    const double r = (b - a) / (b + a);
    const double rho = (sqrt(1.0 - r * r) - 1.0) / r;   // -0.4365
    float c[13];
    c[0] = (float)(log((a + b) * 0.5) - log(1.0 + rho * rho));
    double pk = 1.0;
    for (int k = 1; k <= 12; k++) { pk *= rho; c[k] = (float)(-2.0 * pk / k); }
    const float sc = (float)(1.0 / (b - a));
    const float sh = (float)(a + b);

    const float a5 = c[5] - c[11], a6 = c[6] - c[10], a7 = c[7] - c[9];
    const float b1 = c[1] - c[7] + c[9];
    const float b2 = c[2] - c[6] + c[10];
    const float b3 = c[3] - c[5] + c[11];
    const float b4 = c[4] - c[12];

    init_kernel<<<BATCH * HH / 4 / 256, 256>>>(X, sc, sh);
    ws_kernel<<<CDIM * HH / 256, 256>>>(W);

    dim3 gg(3, BATCH);
    // buffer ids: 0=Y 1=T2 2=T3 3=T4 4=T8 5=U 6=V 7=F
    gemm_sym<0><<<gg, 256>>>(0, 0, 0, 0, 0, 1);   // T2 = 2*Y*Y - I
    gemm_sym<1><<<gg, 256>>>(0, 1, 0, 0, 0, 2);   // T3 = 2*Y*T2 - Y
    gemm_sym<0><<<gg, 256>>>(1, 1, 0, 0, 0, 3);   // T4 = 2*T2*T2 - I
    gemm_sym<0><<<gg, 256>>>(3, 3, 0, 0, 0, 4);   // T8 = 2*T4*T4 - I

    combo_kernel<<<BATCH * HH / 4 / 256, 256>>>(a5, a6, a7,
                                                c[9], c[10], c[11], c[12],
                                                c[0], b1, b2, b3, b4, c[8]);

    gemm_sym<2><<<gg, 256>>>(3, 5, 4, 6, 0, 7);   // F += 2*(T4*U + T8*V), K=512

    center_kernel<<<HH / 256, 256>>>();
    out_kernel<<<BATCH, 256>>>(out);
    p_gemm<<<dim3(2, 2, CDIM), 256>>>();
    gdot_kernel<<<CDIM, 256>>>();
    gfinal_kernel<<<1, 32>>>(out, out_size);
}

// round 15
// speedup vs baseline: 2.3550x; 1.1013x over previous
#include <cuda_runtime.h>
#include <math.h>
#include <stdint.h>

#define BATCH 128
#define HDIM  256
#define CDIM  10
#define HH    (HDIM*HDIM)

// ---------------- static device buffers ----------------
__device__ __align__(128) float g_Y [BATCH*HH];
__device__ __align__(128) float g_T2[BATCH*HH];
__device__ __align__(128) float g_T3[BATCH*HH];
__device__ __align__(128) float g_T4[BATCH*HH];
__device__ __align__(128) float g_T8[BATCH*HH];
__device__ __align__(128) float g_U [BATCH*HH];
__device__ __align__(128) float g_V [BATCH*HH];
__device__ __align__(128) float g_F [BATCH*HH];
__device__ __align__(128) float g_Ws[CDIM*HH];
__device__ __align__(128) float g_Msum[HH];
__device__ __align__(128) float g_center[HH];
__device__ __align__(128) float g_P[CDIM*HH];
__device__ float g_gpart[CDIM];

__device__ __forceinline__ float* bufptr(int id) {
    switch (id) {
        case 0: return g_Y;  case 1: return g_T2; case 2: return g_T3;
        case 3: return g_T4; case 4: return g_T8; case 5: return g_U;
        case 6: return g_V;  default: return g_F;
    }
}

// ---------------- init: Y = (2X - (a+b)I) * sc ----------------
__global__ void init_kernel(const float* __restrict__ X, float sc, float sh)
{
    int q = blockIdx.x * blockDim.x + threadIdx.x;     // over BATCH*HH/4
    float4 x = ((const float4*)X)[q];
    int rem = (q << 2) & (HH - 1);
    int i = rem >> 8;
    int dp = i - (rem & 255);                          // 0..3 if diagonal in this float4
    float4 y;
    y.x = 2.0f * x.x; y.y = 2.0f * x.y; y.z = 2.0f * x.z; y.w = 2.0f * x.w;
    if ((unsigned)dp < 4u) (&y.x)[dp] -= sh;
    y.x *= sc; y.y *= sc; y.z *= sc; y.w *= sc;
    ((float4*)g_Y)[q] = y;
}

// ---------------- Ws = 0.5*(W + W^T) ----------------
__global__ void ws_kernel(const float* __restrict__ W)
{
    int idx = blockIdx.x * blockDim.x + threadIdx.x;   // over CDIM*HH
    int c = idx >> 16;
    int rem = idx & (HH - 1);
    int i = rem >> 8, j = rem & 255;
    g_Ws[idx] = 0.5f * (W[idx] + W[c * HH + j * 256 + i]);
}

// ---------------- symmetric-operand GEMM ----------------
// A operands are SYMMETRIC -> A tile loaded K-MAJOR directly (contiguous).
// grid = (3, BATCH, nz): tile 0=(0,0), 1=(128,128), 2=(128,0)+mirror(0,128)
// MODE 0: C = 2*acc - I
// MODE 1: C = 2*acc - D
// MODE 2: C += 2*acc, K=512 (second phase via A2/B2)
// MODE 3: fused pair over blockIdx.z: z=0 -> MODE1 semantics (C=idc, A=ida,B=idb,D=idd)
//                                     z=1 -> MODE0 semantics (C=idc2, A=ida2,B=idb2)
template<int MODE>
__global__ void __launch_bounds__(256, 3) gemm_sym(int ida, int idb, int ida2,
                                                   int idb2, int idd, int idc,
                                                   int idc2)
{
    __shared__ __align__(16) float As[2][16][128];
    __shared__ __align__(16) float Bs[2][16][128];

    const int z = (MODE == 3) ? blockIdx.z : 0;
    const float* __restrict__ gA  = bufptr((MODE == 3 && z) ? ida2 : ida);
    const float* __restrict__ gB  = bufptr((MODE == 3 && z) ? idb2 : idb);
    const float* __restrict__ gA2 = bufptr(ida2);
    const float* __restrict__ gB2 = bufptr(idb2);
    const float* __restrict__ gD  = bufptr(idd);
    float* __restrict__ gC        = bufptr((MODE == 3 && z) ? idc2 : idc);
    const int em = (MODE == 3) ? (z ? 0 : 1) : MODE;   // effective epilogue mode

    const int b = blockIdx.y;
    const size_t base = (size_t)b * HH;
    const int tile = blockIdx.x;
    const int tm0 = (tile == 0) ? 0 : 128;
    const int tn0 = (tile == 1) ? 128 : 0;
    const int t = threadIdx.x;
    const int tx = t & 15, ty = t >> 4;

    const int crow = t >> 5, ccol = (t & 31) * 4;   // copy row (k), col (4 floats)

    const int KTOT = (MODE == 2) ? 512 : 256;

    uint32_t as0 = (uint32_t)__cvta_generic_to_shared(&As[0][0][0]);
    uint32_t bs0 = (uint32_t)__cvta_generic_to_shared(&Bs[0][0][0]);

    auto issue = [&](int buf, int kg) {
        const float* A = (kg < 256) ? gA : gA2;
        const float* B = (kg < 256) ? gB : gB2;
        int k = kg & 255;
#pragma unroll
        for (int rr = 0; rr < 16; rr += 8) {
            const float* asrc = A + base + (size_t)(k + crow + rr) * 256 + tm0 + ccol;
            const float* bsrc = B + base + (size_t)(k + crow + rr) * 256 + tn0 + ccol;
            uint32_t adst = as0 + (uint32_t)(buf * 2048 + (crow + rr) * 128 + ccol) * 4u;
            uint32_t bdst = bs0 + (uint32_t)(buf * 2048 + (crow + rr) * 128 + ccol) * 4u;
            asm volatile("cp.async.ca.shared.global [%0], [%1], 16;\n" :: "r"(adst), "l"(asrc) : "memory");
            asm volatile("cp.async.ca.shared.global [%0], [%1], 16;\n" :: "r"(bdst), "l"(bsrc) : "memory");
        }
        asm volatile("cp.async.commit_group;\n" ::: "memory");
    };

    float acc[8][8];
#pragma unroll
    for (int i = 0; i < 8; i++)
#pragma unroll
        for (int j = 0; j < 8; j++) acc[i][j] = 0.0f;

    issue(0, 0);
    int cur = 0;
    for (int kg = 0; kg < KTOT; kg += 16) {
        asm volatile("cp.async.wait_group 0;\n" ::: "memory");
        __syncthreads();
        if (kg + 16 < KTOT) issue(cur ^ 1, kg + 16);
#pragma unroll
        for (int kk = 0; kk < 16; kk++) {
            float ar[8], br[8];
            float4 a0 = *(const float4*)&As[cur][kk][ty * 8];
            float4 a1 = *(const float4*)&As[cur][kk][ty * 8 + 4];
            ar[0] = a0.x; ar[1] = a0.y; ar[2] = a0.z; ar[3] = a0.w;
            ar[4] = a1.x; ar[5] = a1.y; ar[6] = a1.z; ar[7] = a1.w;
            float4 b0 = *(const float4*)&Bs[cur][kk][tx * 8];
            float4 b1 = *(const float4*)&Bs[cur][kk][tx * 8 + 4];
            br[0] = b0.x; br[1] = b0.y; br[2] = b0.z; br[3] = b0.w;
            br[4] = b1.x; br[5] = b1.y; br[6] = b1.z; br[7] = b1.w;
#pragma unroll
            for (int i = 0; i < 8; i++)
#pragma unroll
                for (int j = 0; j < 8; j++)
                    acc[i][j] = fmaf(ar[i], br[j], acc[i][j]);
        }
        cur ^= 1;
    }

    // main tile epilogue
#pragma unroll
    for (int i = 0; i < 8; i++) {
        int row = tm0 + ty * 8 + i;
#pragma unroll
        for (int jq = 0; jq < 2; jq++) {
            int col = tn0 + tx * 8 + jq * 4;
            size_t off = base + (size_t)row * 256 + col;
            float4 v;
            v.x = 2.0f * acc[i][jq * 4 + 0];
            v.y = 2.0f * acc[i][jq * 4 + 1];
            v.z = 2.0f * acc[i][jq * 4 + 2];
            v.w = 2.0f * acc[i][jq * 4 + 3];
            if (em == 0) {
                int d = row - col;
                if ((unsigned)d < 4u) (&v.x)[d] -= 1.0f;
            } else if (em == 1) {
                float4 dd = *(const float4*)(gD + off);
                v.x -= dd.x; v.y -= dd.y; v.z -= dd.z; v.w -= dd.w;
            } else {
                float4 f = *(const float4*)(gC + off);
                v.x += f.x; v.y += f.y; v.z += f.z; v.w += f.w;
            }
            *(float4*)(gC + off) = v;
        }
    }

    // mirror tile (transpose) for off-diagonal block
    if (tile == 2) {
#pragma unroll
        for (int j = 0; j < 8; j++) {
            int mrow = tx * 8 + j;                    // tn0 == 0
#pragma unroll
            for (int iq = 0; iq < 2; iq++) {
                int mcol = tm0 + ty * 8 + iq * 4;
                size_t off = base + (size_t)mrow * 256 + mcol;
                float4 v;
                v.x = 2.0f * acc[iq * 4 + 0][j];
                v.y = 2.0f * acc[iq * 4 + 1][j];
                v.z = 2.0f * acc[iq * 4 + 2][j];
                v.w = 2.0f * acc[iq * 4 + 3][j];
                if (em == 1) {
                    float4 dd = *(const float4*)(gD + off);
                    v.x -= dd.x; v.y -= dd.y; v.z -= dd.z; v.w -= dd.w;
                } else if (em == 2) {
                    float4 f = *(const float4*)(gC + off);
                    v.x += f.x; v.y += f.y; v.z += f.z; v.w += f.w;
                }
                *(float4*)(gC + off) = v;
            }
        }
    }
}

// ---------------- combo: U, V, F(=D0) from T1..T4,T8 ----------------
__global__ void combo_kernel(float a5, float a6, float a7,
                             float c9, float c10, float c11, float c12,
                             float c0, float b1, float b2, float b3, float b4,
                             float c8)
{
    int q = blockIdx.x * blockDim.x + threadIdx.x;    // over BATCH*HH/4
    float4 y  = ((const float4*)g_Y )[q];
    float4 t2 = ((const float4*)g_T2)[q];
    float4 t3 = ((const float4*)g_T3)[q];
    float4 t4 = ((const float4*)g_T4)[q];
    float4 t8 = ((const float4*)g_T8)[q];
    float4 u, v, f;
#define EW(e) \
    u.e = a5 * y.e + a6 * t2.e + a7 * t3.e; \
    v.e = c9 * y.e + c10 * t2.e + c11 * t3.e + c12 * t4.e; \
    f.e = b1 * y.e + b2 * t2.e + b3 * t3.e + b4 * t4.e + c8 * t8.e;
    EW(x) EW(y) EW(z) EW(w)
#undef EW
    int rem = (q << 2) & (HH - 1);
    int dp = (rem >> 8) - (rem & 255);
    if ((unsigned)dp < 4u) (&f.x)[dp] += c0;
    ((float4*)g_U)[q] = u;
    ((float4*)g_V)[q] = v;
    ((float4*)g_F)[q] = f;
}

// ---------------- mean over batch (coalesced) ----------------
__global__ void mean_kernel()
{
    int idx = blockIdx.x * blockDim.x + threadIdx.x;   // over HH
    float s = 0.0f;
    for (int b = 0; b < BATCH; b++) s += g_F[(size_t)b * HH + idx];
    g_Msum[idx] = s * (1.0f / BATCH);
}

__global__ void symc_kernel()
{
    int idx = blockIdx.x * blockDim.x + threadIdx.x;   // over HH
    int i = idx >> 8, j = idx & 255;
    g_center[idx] = 0.5f * (g_Msum[idx] + g_Msum[j * 256 + i]);
}

// ---------------- output[b,c] = <Ws[c], F[b]> ----------------
__global__ void out_kernel(float* __restrict__ out)
{
    int b = blockIdx.x, t = threadIdx.x;
    const float4* Fb = (const float4*)(g_F + (size_t)b * HH);
    float acc[CDIM];
#pragma unroll
    for (int c = 0; c < CDIM; c++) acc[c] = 0.0f;
    for (int q = t; q < HH / 4; q += 256) {
        float4 f = Fb[q];
#pragma unroll
        for (int c = 0; c < CDIM; c++) {
            float4 w = ((const float4*)(g_Ws + (size_t)c * HH))[q];
            acc[c] += f.x * w.x + f.y * w.y + f.z * w.z + f.w * w.w;
        }
    }
    __shared__ float red[CDIM][8];
    int lane = t & 31, wp = t >> 5;
#pragma unroll
    for (int c = 0; c < CDIM; c++) {
        float v = acc[c];
        for (int o = 16; o > 0; o >>= 1) v += __shfl_down_sync(0xffffffffu, v, o);
        if (lane == 0) red[c][wp] = v;
    }
    __syncthreads();
    if (t < CDIM) {
        float s = 0.0f;
#pragma unroll
        for (int k = 0; k < 8; k++) s += red[t][k];
        out[b * CDIM + t] = s;
    }
}

// ---------------- P[c] = Ws[c] @ center ----------------
__global__ void __launch_bounds__(256) p_gemm()
{
    const int c = blockIdx.z;
    const float* __restrict__ A  = g_Ws + (size_t)c * HH;
    const float* __restrict__ Bm = g_center;
    float* __restrict__ Cm       = g_P + (size_t)c * HH;
    const int tm0 = blockIdx.y * 128, tn0 = blockIdx.x * 128;

    __shared__ float As[8][132];
    __shared__ float Bs[8][128];
    const int t  = threadIdx.x;
    const int tx = t & 15, ty = t >> 4;
    const int arow = t >> 1, akk = (t & 1) * 4;
    const int brow = t >> 5, bcol = (t & 31) * 4;

    float acc[8][8];
#pragma unroll
    for (int i = 0; i < 8; i++)
#pragma unroll
        for (int j = 0; j < 8; j++) acc[i][j] = 0.0f;

    for (int k0 = 0; k0 < 256; k0 += 8) {
        float4 av = *(const float4*)(A  + (tm0 + arow) * 256 + k0 + akk);
        float4 bv = *(const float4*)(Bm + (k0 + brow) * 256 + tn0 + bcol);
        __syncthreads();
        As[akk + 0][arow] = av.x;
        As[akk + 1][arow] = av.y;
        As[akk + 2][arow] = av.z;
        As[akk + 3][arow] = av.w;
        *(float4*)&Bs[brow][bcol] = bv;
        __syncthreads();
#pragma unroll
        for (int kk = 0; kk < 8; kk++) {
            float ar[8], br[8];
#pragma unroll
            for (int i = 0; i < 8; i++) ar[i] = As[kk][ty * 8 + i];
#pragma unroll
            for (int j = 0; j < 8; j++) br[j] = Bs[kk][tx * 8 + j];
#pragma unroll
            for (int i = 0; i < 8; i++)
#pragma unroll
                for (int j = 0; j < 8; j++)
                    acc[i][j] = fmaf(ar[i], br[j], acc[i][j]);
        }
    }
#pragma unroll
    for (int i = 0; i < 8; i++) {
        int row = tm0 + ty * 8 + i;
#pragma unroll
        for (int jq = 0; jq < 2; jq++) {
            int off = row * 256 + tn0 + tx * 8 + jq * 4;
            float4 v;
            v.x = acc[i][jq * 4 + 0];
            v.y = acc[i][jq * 4 + 1];
            v.z = acc[i][jq * 4 + 2];
            v.w = acc[i][jq * 4 + 3];
            *(float4*)(Cm + off) = v;
        }
    }
}

// ---------------- g[c] = sum_ij P[c,i,j]*P[c,j,i] ----------------
__global__ void gdot_kernel()
{
    int c = blockIdx.x, t = threadIdx.x;
    const float* Pc = g_P + (size_t)c * HH;
    float s = 0.0f;
    for (int idx = t; idx < HH; idx += 256) {
        int i = idx >> 8, j = idx & 255;
        s += Pc[idx] * Pc[j * 256 + i];
    }
    __shared__ float red[8];
    int lane = t & 31, wp = t >> 5;
    for (int o = 16; o > 0; o >>= 1) s += __shfl_down_sync(0xffffffffu, s, o);
    if (lane == 0) red[wp] = s;
    __syncthreads();
    if (t == 0) {
        float v = 0.0f;
#pragma unroll
        for (int k = 0; k < 8; k++) v += red[k];
        g_gpart[c] = v;
    }
}

__global__ void gfinal_kernel(float* __restrict__ out, int out_size)
{
    if (threadIdx.x == 0) {
        float s = 0.0f;
#pragma unroll
        for (int c = 0; c < CDIM; c++) s += g_gpart[c];
        s *= (1.0f / CDIM);
        if (out_size > BATCH * CDIM) out[BATCH * CDIM] = s;
    }
}

// ---------------- host ----------------
extern "C" void kernel_launch(void* const* d_in, const int* in_sizes, int n_in,
                              void* d_out, int out_size)
{
    const float* X = (const float*)d_in[0];   // mat_feats [128,256,256]
    const float* W = (const float*)d_in[1];   // W        [10,256,256]
    float* out = (float*)d_out;

    // Chebyshev coefficients of log on [a,b]: log(A+Bt) = logC - 2 sum rho^k/k T_k
    const double a = 1.0, b = 6.5;
    const double r = (b - a) / (b + a);
    const double rho = (sqrt(1.0 - r * r) - 1.0) / r;   // -0.4365
    float c[13];
    c[0] = (float)(log((a + b) * 0.5) - log(1.0 + rho * rho));
    double pk = 1.0;
    for (int k = 1; k <= 12; k++) { pk *= rho; c[k] = (float)(-2.0 * pk / k); }
    const float sc = (float)(1.0 / (b - a));
    const float sh = (float)(a + b);

    const float a5 = c[5] - c[11], a6 = c[6] - c[10], a7 = c[7] - c[9];
    const float b1 = c[1] - c[7] + c[9];
    const float b2 = c[2] - c[6] + c[10];
    const float b3 = c[3] - c[5] + c[11];
    const float b4 = c[4] - c[12];

    init_kernel<<<BATCH * HH / 4 / 256, 256>>>(X, sc, sh);
    ws_kernel<<<CDIM * HH / 256, 256>>>(W);

    // buffer ids: 0=Y 1=T2 2=T3 3=T4 4=T8 5=U 6=V 7=F
    gemm_sym<0><<<dim3(3, BATCH, 1), 256>>>(0, 0, 0, 0, 0, 1, 0); // T2 = 2*Y*Y - I
    gemm_sym<3><<<dim3(3, BATCH, 2), 256>>>(0, 1, 1, 1, 0, 2, 3); // z0: T3 = 2*Y*T2 - Y
                                                                  // z1: T4 = 2*T2*T2 - I
    gemm_sym<0><<<dim3(3, BATCH, 1), 256>>>(3, 3, 0, 0, 0, 4, 0); // T8 = 2*T4*T4 - I

    combo_kernel<<<BATCH * HH / 4 / 256, 256>>>(a5, a6, a7,
                                                c[9], c[10], c[11], c[12],
                                                c[0], b1, b2, b3, b4, c[8]);

    gemm_sym<2><<<dim3(3, BATCH, 1), 256>>>(3, 5, 4, 6, 0, 7, 0); // F += 2*(T4*U + T8*V)

    mean_kernel<<<HH / 256, 256>>>();
    symc_kernel<<<HH / 256, 256>>>();
    out_kernel<<<BATCH, 256>>>(out);
    p_gemm<<<dim3(2, 2, CDIM), 256>>>();
    gdot_kernel<<<CDIM, 256>>>();
    gfinal_kernel<<<1, 32>>>(out, out_size);
}